// round 4
// baseline (speedup 1.0000x reference)
#include <cuda_runtime.h>
#include <math.h>

#define BS 8
#define QN 1000
#define NC 92
#define TN 300
#define QP1 1001
#define TP1 301
#define SCSZ (BS*QP1*TP1)          // 2,410,408
#define MTROW (QN+TN)              // 1300
#define ROWW 20                    // packed words per row (10 warps * 2)
#define NWARP 10
#define CHUNK 250                  // traceback rows staged per smem load

__device__ float g_prob[BS*QN*NC];
__device__ float g_cost[BS*QN*TN];
__device__ unsigned g_packed[BS*QP1*ROWW];   // 2-bit pointer codes, 640KB
__device__ int g_lbl64;                      // 1 if labels are int64, 0 if int32

// ---------------- label dtype detection ----------------
// int64 labels in [0,92): odd 32-bit words all zero. int32 labels: odd words
// are labels themselves (P(all 8 zero) ~ (1/92)^8 ~ 0).
__global__ void detect_kernel(const unsigned* __restrict__ lbl_raw) {
    int allzero = 1;
    #pragma unroll
    for (int k = 1; k < 16; k += 2) allzero &= (lbl_raw[k] == 0u);
    g_lbl64 = allzero;
}

// ---------------- softmax over logits [BS*QN, NC] -> g_prob ----------------
__global__ void softmax_kernel(const float* __restrict__ logits) {
    int warpId = (blockIdx.x * blockDim.x + threadIdx.x) >> 5;
    int lane = threadIdx.x & 31;
    if (warpId >= BS * QN) return;
    const float* row = logits + warpId * NC;
    float v0 = (lane < NC)      ? row[lane]      : -INFINITY;
    float v1 = (lane + 32 < NC) ? row[lane + 32] : -INFINITY;
    float v2 = (lane + 64 < NC) ? row[lane + 64] : -INFINITY;
    float m = fmaxf(v0, fmaxf(v1, v2));
    #pragma unroll
    for (int o = 16; o; o >>= 1) m = fmaxf(m, __shfl_xor_sync(0xffffffffu, m, o));
    float e0 = (lane < NC)      ? expf(v0 - m) : 0.f;
    float e1 = (lane + 32 < NC) ? expf(v1 - m) : 0.f;
    float e2 = (lane + 64 < NC) ? expf(v2 - m) : 0.f;
    float s = e0 + e1 + e2;
    #pragma unroll
    for (int o = 16; o; o >>= 1) s += __shfl_xor_sync(0xffffffffu, s, o);
    float* out = g_prob + warpId * NC;
    if (lane < NC)      out[lane]      = e0 / s;
    if (lane + 32 < NC) out[lane + 32] = e1 / s;
    if (lane + 64 < NC) out[lane + 64] = e2 / s;
}

// ---------------- cost matrix [BS, QN, TN] -> g_cost ----------------
__global__ void cost_kernel(const float* __restrict__ pred_boxes,
                            const int* __restrict__ tgt_labels,
                            const float* __restrict__ tgt_boxes) {
    int idx = blockIdx.x * blockDim.x + threadIdx.x;
    if (idx >= BS * QN * TN) return;
    int t = idx % TN;
    int bq = idx / TN;           // b*QN + q
    int b = bq / QN;

    float4 pb = ((const float4*)pred_boxes)[bq];
    float4 tb = ((const float4*)tgt_boxes)[b * TN + t];
    int li = b * TN + t;
    int lbl = g_lbl64 ? tgt_labels[li * 2] : tgt_labels[li];   // low word if int64
    lbl = max(0, min(NC - 1, lbl));                            // never fault
    float p = g_prob[bq * NC + lbl];

    float l1 = fabsf(pb.x - tb.x) + fabsf(pb.y - tb.y) +
               fabsf(pb.z - tb.z) + fabsf(pb.w - tb.w);

    float px1 = pb.x - 0.5f * pb.z, py1 = pb.y - 0.5f * pb.w;
    float px2 = pb.x + 0.5f * pb.z, py2 = pb.y + 0.5f * pb.w;
    float tx1 = tb.x - 0.5f * tb.z, ty1 = tb.y - 0.5f * tb.w;
    float tx2 = tb.x + 0.5f * tb.z, ty2 = tb.y + 0.5f * tb.w;

    float a1 = (px2 - px1) * (py2 - py1);
    float a2 = (tx2 - tx1) * (ty2 - ty1);
    float ltx = fmaxf(px1, tx1), lty = fmaxf(py1, ty1);
    float rbx = fminf(px2, tx2), rby = fminf(py2, ty2);
    float iw = fmaxf(rbx - ltx, 0.f), ih = fmaxf(rby - lty, 0.f);
    float inter = iw * ih;
    float uni = a1 + a2 - inter;
    float iou = inter / uni;
    float cx1 = fminf(px1, tx1), cy1 = fminf(py1, ty1);
    float cx2 = fmaxf(px2, tx2), cy2 = fmaxf(py2, ty2);
    float cw = fmaxf(cx2 - cx1, 0.f), ch = fmaxf(cy2 - cy1, 0.f);
    float ac = cw * ch;
    float giou = iou - (ac - uni) / ac;

    g_cost[idx] = 5.0f * l1 - p - 2.0f * giou;
}

// ---------------- DP + traceback: one block per batch ----------------
// out layout (float32): [scores 8x1001x301][pointers 8x1001x301][matches 8x1300x2]
__global__ void __launch_bounds__(320, 1) dp_kernel(float* __restrict__ out) {
    __shared__ float bufA[TP1 + 1];
    __shared__ float bufB[TP1 + 1];
    __shared__ float warpTot[NWARP];
    __shared__ unsigned chunkBuf[CHUNK * ROWW];   // 20 KB

    int b = blockIdx.x;
    int tid = threadIdx.x;
    int lane = tid & 31;
    int w = tid >> 5;
    int j = tid + 1;                 // column this thread owns (1..300)
    bool valid = tid < TN;

    float* scores = out + (size_t)b * QP1 * TP1;
    float* ptrs   = out + SCSZ + (size_t)b * QP1 * TP1;
    unsigned* pk  = g_packed + (size_t)b * QP1 * ROWW;

    // boundaries: row 0, col 0
    for (int k = tid; k < TP1; k += blockDim.x) {
        scores[k] = 0.f;
        ptrs[k] = (k == 0) ? 0.f : 1.f;
    }
    for (int k = tid + 1; k <= QN; k += blockDim.x) {
        scores[(size_t)k * TP1] = 0.f;
        ptrs[(size_t)k * TP1] = -1.f;
    }
    if (tid == 0) { bufA[0] = 0.f; bufB[0] = 0.f; }
    if (valid) bufA[j] = 0.f;        // scores row 0 = 0
    __syncthreads();

    const float* costRow = g_cost + (size_t)b * QN * TN;
    float* prevB = bufA;
    float* curB = bufB;

    float cst = valid ? costRow[tid] : 0.f;     // prefetch row 1

    for (int i = 1; i <= QN; i++) {
        float diag = 0.f, up = 0.f;
        float v = -INFINITY;
        if (valid) {
            float r = 10000.0f - cst;
            float pl = prevB[tid];       // scores[i-1][j-1]
            up = prevB[j];               // scores[i-1][j]
            diag = pl + r;
            v = fmaxf(diag, up);
        }
        // prefetch next row's cost (overlaps scan + barriers)
        float cstN = (valid && i < QN) ? costRow[(size_t)i * TN + tid] : 0.f;

        // inclusive warp prefix-max
        #pragma unroll
        for (int o = 1; o < 32; o <<= 1) {
            float t2 = __shfl_up_sync(0xffffffffu, v, o);
            if (lane >= o) v = fmaxf(v, t2);
        }
        if (lane == 31) warpTot[w] = v;
        __syncthreads();
        float off = -INFINITY;
        #pragma unroll
        for (int ww = 0; ww < NWARP - 1; ww++)
            if (ww < w) off = fmaxf(off, warpTot[ww]);
        float s = fmaxf(v, off);

        int e = 0;                       // 0=diag, 1=up, 2=left
        if (valid) {
            e = (diag == s) ? 0 : ((up == s) ? 1 : 2);
            curB[j] = s;
            scores[(size_t)i * TP1 + j] = s;
            ptrs[(size_t)i * TP1 + j] = (e == 0) ? 0.f : ((e == 1) ? -1.f : 1.f);
        }
        unsigned b0 = __ballot_sync(0xffffffffu, valid && (e & 1));
        unsigned b1 = __ballot_sync(0xffffffffu, valid && (e >> 1));
        if (lane == 0) {
            pk[i * ROWW + w * 2]     = b0;
            pk[i * ROWW + w * 2 + 1] = b1;
        }
        if (tid == 0) curB[0] = 0.f;
        __syncthreads();
        float* tmp = prevB; prevB = curB; curB = tmp;
        cst = cstN;
    }

    // ---- traceback, chunked through smem ----
    float* mt = out + 2 * (size_t)SCSZ + (size_t)b * MTROW * 2;
    int r = QN, c = TN, st = 0;

    #pragma unroll 1
    for (int k = 0; k < QN / CHUNK; k++) {
        int hi = QN - k * CHUNK;         // 1000, 750, 500, 250
        int lo = hi - (CHUNK - 1);       // 751, 501, 251, 1
        const unsigned* src = pk + (size_t)lo * ROWW;
        for (int x = tid; x < CHUNK * ROWW; x += 320) chunkBuf[x] = src[x];
        __syncthreads();
        if (tid == 0) {
            while (st < MTROW && r >= lo) {
                int p;
                if (c == 0) {
                    p = -1;
                } else {
                    int ci = c - 1;
                    int ww = ci >> 5, ll = ci & 31;
                    unsigned w0 = chunkBuf[(r - lo) * ROWW + ww * 2];
                    unsigned w1 = chunkBuf[(r - lo) * ROWW + ww * 2 + 1];
                    int e = ((w0 >> ll) & 1) | (((w1 >> ll) & 1) << 1);
                    p = (e == 0) ? 0 : ((e == 1) ? -1 : 1);
                }
                int nr = (p == 1) ? r : r - 1;
                int nc = (p == -1) ? c : c - 1;
                bool ismatch = (p == 0);
                int oidx = (MTROW - 1 - st) * 2;
                mt[oidx]     = ismatch ? (float)nr : -1.f;
                mt[oidx + 1] = ismatch ? (float)nc : -1.f;
                r = nr; c = nc; st++;
            }
        }
        __syncthreads();
    }
    // r == 0 now: all remaining steps emit (-1,-1)
    if (tid == 0) {
        while (st < MTROW) {
            int oidx = (MTROW - 1 - st) * 2;
            mt[oidx] = -1.f;
            mt[oidx + 1] = -1.f;
            st++;
        }
    }
}

extern "C" void kernel_launch(void* const* d_in, const int* in_sizes, int n_in,
                              void* d_out, int out_size) {
    const float* pred_logits = (const float*)d_in[0];
    const float* pred_boxes  = (const float*)d_in[1];
    const int*   tgt_labels  = (const int*)d_in[2];   // int32 or int64 (detected)
    const float* tgt_boxes   = (const float*)d_in[3];
    float* out = (float*)d_out;

    // label dtype detection (1 thread, reads 16 words)
    detect_kernel<<<1, 1>>>((const unsigned*)d_in[2]);
    // softmax: 8000 rows, one warp each
    softmax_kernel<<<(BS * QN + 7) / 8, 256>>>(pred_logits);
    // cost: 2.4M cells
    cost_kernel<<<(BS * QN * TN + 255) / 256, 256>>>(pred_boxes, tgt_labels, tgt_boxes);
    // DP + traceback: one block per batch
    dp_kernel<<<BS, 320>>>(out);
}